// round 7
// baseline (speedup 1.0000x reference)
#include <cuda_runtime.h>
#include <cstdint>

#define BATCH   8192
#define NF      128          // in_features == out_features == 128
#define NH      64
#define SPLIT   4            // CTAs per head
#define THREADS 256
#define MAXROWS 1024         // per-head row-list capacity (binomial max ~165)
#define SMEM_W  65536        // 128x128 fp32 weights
#define SMEM_X  32768        // 8 warps * 4 rows * 128 * 8B (x duplicated {v,v})
#define SMEM_BYTES (SMEM_W + SMEM_X + MAXROWS * 4)

typedef unsigned long long ull;

// Compacted per-row head ids (filled by lm_prep). Static device global: allowed scratch.
__device__ __align__(16) unsigned char g_heads[BATCH];

__device__ __forceinline__ ull fma2(ull a, ull b, ull c) {
    ull d;
    asm("fma.rn.f32x2 %0, %1, %2, %3;" : "=l"(d) : "l"(a), "l"(b), "l"(c));
    return d;
}
__device__ __forceinline__ float f2lo(ull v) { return __uint_as_float((unsigned int)v); }
__device__ __forceinline__ float f2hi(ull v) { return __uint_as_float((unsigned int)(v >> 32)); }

// ---------------------------------------------------------------------------
// Prep: detect head_ix dtype (int64 vs int32) and compact to uint8.
// If the buffer holds int64 values in [0,64), every odd 32-bit word of the
// first 8192 words is exactly 0. If it holds int32 heads, ~63/64 of those
// 4096 words are nonzero. Deterministic given the input.
// ---------------------------------------------------------------------------
__global__ void lm_prep(const void* __restrict__ hx) {
    const int* wds = (const int*)hx;
    __shared__ int s_any;
    if (threadIdx.x == 0) s_any = 0;
    __syncthreads();
    int a = 0;
    for (int j = threadIdx.x; j < BATCH / 2; j += blockDim.x)
        a |= wds[2 * j + 1];
    if (a) atomicOr(&s_any, 1);
    __syncthreads();
    const bool is64 = (s_any == 0);
    const long long* w64 = (const long long*)hx;
    const int stride = gridDim.x * blockDim.x;
    for (int b = blockIdx.x * blockDim.x + threadIdx.x; b < BATCH; b += stride) {
        int hv = is64 ? (int)w64[b] : wds[b];
        g_heads[b] = (unsigned char)hv;
    }
}

// ---------------------------------------------------------------------------
// Main: grid = NH*SPLIT CTAs. CTA (h, s):
//   - stage W[h] (64KB) into SMEM
//   - build ordered row list for head h via block scan over g_heads (8KB)
//   - each warp: 4 rows x 128 outputs, 8 packed f32x2 accumulators
// ---------------------------------------------------------------------------
__global__ void __launch_bounds__(THREADS) lm_main(
    const float* __restrict__ x, const float* __restrict__ wgt,
    const float* __restrict__ bias, float* __restrict__ out)
{
    extern __shared__ unsigned char smem[];
    float4* Wsm  = reinterpret_cast<float4*>(smem);
    ull*    Xs   = reinterpret_cast<ull*>(smem + SMEM_W);
    int*    rowsm = reinterpret_cast<int*>(smem + SMEM_W + SMEM_X);
    __shared__ int sc[THREADS];

    const int tid = threadIdx.x;
    const int h   = blockIdx.x / SPLIT;
    const int s   = blockIdx.x % SPLIT;

    // --- Stage weights: 4096 float4 over 256 threads ---
    const float4* wg = reinterpret_cast<const float4*>(wgt) + (size_t)h * (NF * NF / 4);
    #pragma unroll
    for (int i = 0; i < (NF * NF / 4) / THREADS; i++)
        Wsm[i * THREADS + tid] = wg[i * THREADS + tid];

    // --- Ordered compaction of rows with head == h (stable => ascending) ---
    union { uint4 v[2]; unsigned char b[32]; } u;
    const uint4* hp = reinterpret_cast<const uint4*>(g_heads);
    u.v[0] = hp[tid * 2];
    u.v[1] = hp[tid * 2 + 1];
    int cnt = 0;
    #pragma unroll
    for (int j = 0; j < 32; j++) cnt += (u.b[j] == h);
    sc[tid] = cnt;
    __syncthreads();
    for (int off = 1; off < THREADS; off <<= 1) {
        int v = (tid >= off) ? sc[tid - off] : 0;
        __syncthreads();
        sc[tid] += v;
        __syncthreads();
    }
    int n = sc[THREADS - 1];
    if (n > MAXROWS) n = MAXROWS;   // safety only; statistically impossible here
    int wr = sc[tid] - cnt;
    #pragma unroll
    for (int j = 0; j < 32; j++) {
        if (u.b[j] == h) {
            if (wr < MAXROWS) rowsm[wr] = tid * 32 + j;
            wr++;
        }
    }
    __syncthreads();

    const int warp = tid >> 5, lane = tid & 31;
    ull* Xw = Xs + warp * (4 * NF);
    const uint32_t wbase = (uint32_t)__cvta_generic_to_shared(Wsm) + lane * 16;

    for (int g = s * 8 + warp; g * 4 < n; g += SPLIT * 8) {
        const int r0 = g * 4;
        int rws[4];
        #pragma unroll
        for (int r = 0; r < 4; r++) rws[r] = (r0 + r < n) ? rowsm[r0 + r] : -1;

        // Stage x rows into SMEM, each value duplicated {v,v} (zero-pack FMA2 ops)
        #pragma unroll
        for (int r = 0; r < 4; r++) {
            const bool valid = rws[r] >= 0;
            const float* xr = x + (size_t)(valid ? rws[r] : 0) * NF;
            #pragma unroll
            for (int k = 0; k < 4; k++) {
                const int col = lane + k * 32;
                float v = valid ? xr[col] : 0.f;
                unsigned int uu = __float_as_uint(v);
                Xw[r * NF + col] = (ull)uu | ((ull)uu << 32);
            }
        }
        __syncwarp();

        ull acc[8];
        #pragma unroll
        for (int q = 0; q < 8; q++) acc[q] = 0ull;

        // Inner product over i: per step 1 LDS.v2.u64 (W pair, conflict-free),
        // 4 broadcast LDS.64 (x), 8 fma.rn.f32x2 (= 16 fp32 FMAs).
        #pragma unroll 8
        for (int i = 0; i < NF; i++) {
            ull w01, w23;
            asm volatile("ld.shared.v2.u64 {%0, %1}, [%2];"
                         : "=l"(w01), "=l"(w23)
                         : "r"(wbase + i * 512));
            #pragma unroll
            for (int r = 0; r < 4; r++) {
                ull xv = Xw[r * NF + i];
                acc[2 * r]     = fma2(xv, w01, acc[2 * r]);
                acc[2 * r + 1] = fma2(xv, w23, acc[2 * r + 1]);
            }
        }

        // Epilogue: + bias, STG.128 per row
        const int o = lane * 4;
        const float4 bv = *reinterpret_cast<const float4*>(bias + h * NF + o);
        #pragma unroll
        for (int r = 0; r < 4; r++) {
            if (rws[r] >= 0) {
                float4 res;
                res.x = f2lo(acc[2 * r])     + bv.x;
                res.y = f2hi(acc[2 * r])     + bv.y;
                res.z = f2lo(acc[2 * r + 1]) + bv.z;
                res.w = f2hi(acc[2 * r + 1]) + bv.w;
                *reinterpret_cast<float4*>(out + (size_t)rws[r] * NF + o) = res;
            }
        }
        __syncwarp();   // Xw reuse barrier for next group
    }
}

extern "C" void kernel_launch(void* const* d_in, const int* in_sizes, int n_in,
                              void* d_out, int out_size) {
    const float* x    = (const float*)d_in[0];
    const float* w    = (const float*)d_in[1];
    const float* b    = (const float*)d_in[2];
    const void*  hx   = d_in[3];   // int64 or int32, detected on-device
    float*       out  = (float*)d_out;

    cudaFuncSetAttribute(lm_main, cudaFuncAttributeMaxDynamicSharedMemorySize, SMEM_BYTES);

    lm_prep<<<32, 256>>>(hx);
    lm_main<<<NH * SPLIT, THREADS, SMEM_BYTES>>>(x, w, b, out);
}